// round 4
// baseline (speedup 1.0000x reference)
#include <cuda_runtime.h>
#include <math.h>

#define N_NODES  100000
#define N_EDGES  3200000
#define N_GRAPHS 512
#define F_IN     128
#define F_HID    64
#define F_OUT    10

#define SCAN_B   512
#define NBLK     ((N_NODES + SCAN_B - 1) / SCAN_B)   // 196

// ---------------- scratch (device globals: no allocation allowed) ----------
__device__ int   g_count [N_NODES];        // in-degree
__device__ int   g_cursor[N_NODES];        // scatter cursors
__device__ int   g_off   [N_NODES + 1];    // CSR row offsets (by dst)
__device__ int   g_bsum  [NBLK];
__device__ int   g_boff  [NBLK];
__device__ int   g_src   [N_EDGES];        // CSR: source node per slot
__device__ float g_dinv  [N_NODES];
__device__ float g_h     [N_NODES * F_HID];   // GEMM out, pre-scaled by dinv
__device__ float g_x1    [N_NODES * F_HID];
__device__ float g_x2    [N_NODES * F_HID];
__device__ float g_x3    [N_NODES * F_HID];
__device__ int   g_start [N_GRAPHS + 1];   // graph -> first node (batch sorted)
__device__ float g_pool  [N_GRAPHS * 3 * F_HID];

// ---------------- prep -------------------------------------------------------
__global__ void zero_ints_kernel() {
    int i = blockIdx.x * blockDim.x + threadIdx.x;
    int stride = gridDim.x * blockDim.x;
    for (int k = i; k < N_NODES; k += stride) { g_count[k] = 0; g_cursor[k] = 0; }
}

__global__ void count_kernel(const int* __restrict__ ei) {
    int e = blockIdx.x * blockDim.x + threadIdx.x;
    if (e >= N_EDGES) return;
    unsigned c = (unsigned)ei[N_EDGES + e];
    if (c < N_NODES) atomicAdd(&g_count[c], 1);
}

__global__ void dinv_kernel() {
    int i = blockIdx.x * blockDim.x + threadIdx.x;
    if (i >= N_NODES) return;
    int d = g_count[i];
    g_dinv[i] = (d > 0) ? rsqrtf((float)d) : 0.0f;
}

// ---- 3-kernel exclusive scan of g_count -> g_off ---------------------------
__global__ void scan1_kernel() {
    __shared__ int s[SCAN_B];
    int t = threadIdx.x;
    int i = blockIdx.x * SCAN_B + t;
    int v = (i < N_NODES) ? g_count[i] : 0;
    s[t] = v; __syncthreads();
    int x = v;
    for (int o = 1; o < SCAN_B; o <<= 1) {
        int y = (t >= o) ? s[t - o] : 0;
        __syncthreads();
        x += y; s[t] = x;
        __syncthreads();
    }
    if (i < N_NODES) g_off[i] = x - v;            // exclusive
    if (t == SCAN_B - 1) g_bsum[blockIdx.x] = x;  // block total
}

__global__ void scan2_kernel() {     // single block of 256 (NBLK <= 256)
    __shared__ int s[256];
    int t = threadIdx.x;
    int v = (t < NBLK) ? g_bsum[t] : 0;
    s[t] = v; __syncthreads();
    int x = v;
    for (int o = 1; o < 256; o <<= 1) {
        int y = (t >= o) ? s[t - o] : 0;
        __syncthreads();
        x += y; s[t] = x;
        __syncthreads();
    }
    if (t < NBLK) g_boff[t] = x - v;
}

__global__ void scan3_kernel() {
    int i = blockIdx.x * blockDim.x + threadIdx.x;
    if (i < N_NODES) g_off[i] += g_boff[i / SCAN_B];
    if (i == 0) g_off[N_NODES] = N_EDGES;
}

__global__ void scatter_kernel(const int* __restrict__ ei) {
    int e = blockIdx.x * blockDim.x + threadIdx.x;
    if (e >= N_EDGES) return;
    int r = ei[e];
    unsigned c = (unsigned)ei[N_EDGES + e];
    if (c >= N_NODES) return;
    int pos = g_off[c] + atomicAdd(&g_cursor[c], 1);
    g_src[pos] = r;
}

// ---------------- GEMM: h[n,64] = (X[n,:K] @ W) * dinv[n] -------------------
// src: 0 -> Xext, 1 -> g_x1, 2 -> g_x2.  256 thr = 4 nodes x 64 feats.
template <int K>
__global__ void gemm_kernel(const float* __restrict__ Xext,
                            const float* __restrict__ W, int src) {
    __shared__ float sW[K * F_HID];
    for (int i = threadIdx.x; i < K * F_HID; i += 256) sW[i] = W[i];
    __syncthreads();

    int node = blockIdx.x * 4 + (threadIdx.x >> 6);
    int f    = threadIdx.x & 63;
    if (node >= N_NODES) return;

    const float* X = (src == 0) ? Xext : (src == 1) ? g_x1 : g_x2;
    const float* xr = X + (size_t)node * K;
    float acc = 0.0f;
#pragma unroll 8
    for (int k = 0; k < K; k++)
        acc = fmaf(xr[k], sW[k * F_HID + f], acc);
    g_h[node * F_HID + f] = acc * g_dinv[node];
}

// ---------------- aggregate (CSR gather) + bias + relu ----------------------
// out[n,f] = relu( dinv[n] * sum_{e in in(n)} g_h[src(e), f] + b[f] )
__global__ void aggregate_kernel(const float* __restrict__ b, int dst) {
    int node = blockIdx.x * 4 + (threadIdx.x >> 6);
    int f    = threadIdx.x & 63;
    if (node >= N_NODES) return;

    int beg = g_off[node], end = g_off[node + 1];
    float a0 = 0.f, a1 = 0.f, a2 = 0.f, a3 = 0.f;
    int e = beg;
    for (; e + 4 <= end; e += 4) {              // 4-way MLP
        int s0 = g_src[e + 0], s1 = g_src[e + 1];
        int s2 = g_src[e + 2], s3 = g_src[e + 3];
        a0 += g_h[s0 * F_HID + f];
        a1 += g_h[s1 * F_HID + f];
        a2 += g_h[s2 * F_HID + f];
        a3 += g_h[s3 * F_HID + f];
    }
    for (; e < end; e++) a0 += g_h[g_src[e] * F_HID + f];
    float acc = (a0 + a1) + (a2 + a3);

    float v = fmaxf(acc * g_dinv[node] + b[f], 0.0f);
    float* out = (dst == 1) ? g_x1 : (dst == 2) ? g_x2 : g_x3;
    out[node * F_HID + f] = v;
}

// ---------------- pooling over sorted batch ---------------------------------
__global__ void start_mark_kernel() {
    int i = blockIdx.x * blockDim.x + threadIdx.x;
    if (i <= N_GRAPHS) g_start[i] = -1;
}

__global__ void start_set_kernel(const int* __restrict__ batch) {
    int i = blockIdx.x * blockDim.x + threadIdx.x;
    if (i >= N_NODES) return;
    int bcur = batch[i];
    if ((unsigned)bcur >= N_GRAPHS) return;
    if (i == 0 || batch[i - 1] != bcur) g_start[bcur] = i;
    if (i == 0) g_start[N_GRAPHS] = N_NODES;
}

__global__ void start_fix_kernel() {      // backward fill for empty graphs
    __shared__ int s[N_GRAPHS + 1];
    int t = threadIdx.x;
    for (int k = t; k <= N_GRAPHS; k += blockDim.x) s[k] = g_start[k];
    __syncthreads();
    if (t == 0) {
        int nxt = s[N_GRAPHS];
        for (int g = N_GRAPHS - 1; g >= 0; --g) {
            if (s[g] < 0) s[g] = nxt;
            nxt = s[g];
        }
    }
    __syncthreads();
    for (int k = t; k <= N_GRAPHS; k += blockDim.x) g_start[k] = s[k];
}

// one block (192 thr) per graph: mean over its contiguous node range
__global__ void pool_kernel() {
    int g = blockIdx.x;
    int t = threadIdx.x;                  // 0..191
    int beg = g_start[g], end = g_start[g + 1];
    const float* src = (t < 64) ? g_x1 : (t < 128) ? g_x2 : g_x3;
    int f = t & 63;
    float acc = 0.0f;
    for (int n = beg; n < end; n++) acc += src[n * F_HID + f];
    float cnt = (float)max(end - beg, 1);
    g_pool[g * (3 * F_HID) + t] = acc / cnt;
}

// one warp per graph: logits = pooled @ Wf + bf, softmax over 10
__global__ void final_kernel(const float* __restrict__ Wf,
                             const float* __restrict__ bf,
                             float* __restrict__ out) {
    int g = blockIdx.x;
    int j = threadIdx.x;
    float logit = __int_as_float(0xff800000);  // -inf
    if (j < F_OUT) {
        float acc = bf[j];
        const float* p = g_pool + g * (3 * F_HID);
#pragma unroll 16
        for (int k = 0; k < 3 * F_HID; k++)
            acc = fmaf(p[k], Wf[k * F_OUT + j], acc);
        logit = acc;
    }
    float m = logit;
    for (int o = 16; o; o >>= 1) m = fmaxf(m, __shfl_xor_sync(0xffffffff, m, o));
    float ex = (j < F_OUT) ? expf(logit - m) : 0.0f;
    float s = ex;
    for (int o = 16; o; o >>= 1) s += __shfl_xor_sync(0xffffffff, s, o);
    if (j < F_OUT) out[g * F_OUT + j] = ex / s;
}

// ---------------- launch -----------------------------------------------------
// Kernel launches only — capture-safe, no runtime API calls.
extern "C" void kernel_launch(void* const* d_in, const int* in_sizes, int n_in,
                              void* d_out, int out_size) {
    const float* X0    = (const float*)d_in[0];
    const int*   ei    = (const int*)d_in[1];    // int32! (JAX x64 disabled)
    const int*   batch = (const int*)d_in[2];    // int32!
    const float* W1    = (const float*)d_in[3];
    const float* b1    = (const float*)d_in[4];
    const float* W2    = (const float*)d_in[5];
    const float* b2    = (const float*)d_in[6];
    const float* W3    = (const float*)d_in[7];
    const float* b3    = (const float*)d_in[8];
    const float* Wf    = (const float*)d_in[9];
    const float* bf    = (const float*)d_in[10];
    float* out = (float*)d_out;

    const int TB = 256;
    const int gridE = (N_EDGES + TB - 1) / TB;
    const int gridN = (N_NODES + TB - 1) / TB;
    const int gridG = (N_NODES + 3) / 4;      // gemm / aggregate (4 nodes/blk)

    // --- CSR + norm prep ---
    zero_ints_kernel<<<256, TB>>>();
    count_kernel<<<gridE, TB>>>(ei);
    dinv_kernel<<<gridN, TB>>>();
    scan1_kernel<<<NBLK, SCAN_B>>>();
    scan2_kernel<<<1, 256>>>();
    scan3_kernel<<<gridN, TB>>>();
    scatter_kernel<<<gridE, TB>>>(ei);

    // --- graph boundaries (batch is sorted) ---
    start_mark_kernel<<<4, TB>>>();
    start_set_kernel<<<gridN, TB>>>(batch);
    start_fix_kernel<<<1, 256>>>();

    // --- layer 1 ---
    gemm_kernel<F_IN><<<gridG, TB>>>(X0, W1, 0);
    aggregate_kernel<<<gridG, TB>>>(b1, 1);
    // --- layer 2 ---
    gemm_kernel<F_HID><<<gridG, TB>>>(nullptr, W2, 1);
    aggregate_kernel<<<gridG, TB>>>(b2, 2);
    // --- layer 3 ---
    gemm_kernel<F_HID><<<gridG, TB>>>(nullptr, W3, 2);
    aggregate_kernel<<<gridG, TB>>>(b3, 3);

    // --- pooling + head ---
    pool_kernel<<<N_GRAPHS, 3 * F_HID>>>();
    final_kernel<<<N_GRAPHS, 32>>>(Wf, bf, out);
}

// round 5
// speedup vs baseline: 1.4871x; 1.4871x over previous
#include <cuda_runtime.h>
#include <cuda_fp16.h>
#include <math.h>

#define N_NODES  100000
#define N_EDGES  3200000
#define N_GRAPHS 512
#define F_IN     128
#define F_HID    64
#define F_OUT    10

#define SCAN_B   512
#define NBLK     ((N_NODES + SCAN_B - 1) / SCAN_B)   // 196

// ---------------- scratch (device globals: no allocation allowed) ----------
__device__ int     g_count [N_NODES];
__device__ int     g_cursor[N_NODES];
__device__ int     g_off   [N_NODES + 1];
__device__ int     g_bsum  [NBLK];
__device__ int     g_boff  [NBLK];
__device__ int     g_src   [N_EDGES];
__device__ float   g_dinv  [N_NODES];
__device__ __half2 g_h2    [N_NODES * 32];        // h in fp16, pre-scaled by dinv
__device__ float   g_x1    [N_NODES * F_HID];
__device__ float   g_x2    [N_NODES * F_HID];
__device__ float   g_x3    [N_NODES * F_HID];
__device__ int     g_start [N_GRAPHS + 1];
__device__ float   g_pool  [N_GRAPHS * 3 * F_HID];

// ---------------- prep -------------------------------------------------------
__global__ void zero_ints_kernel() {
    int i = blockIdx.x * blockDim.x + threadIdx.x;
    int stride = gridDim.x * blockDim.x;
    for (int k = i; k < N_NODES; k += stride) { g_count[k] = 0; g_cursor[k] = 0; }
}

__global__ void count_kernel(const int* __restrict__ ei) {
    int e = blockIdx.x * blockDim.x + threadIdx.x;
    if (e >= N_EDGES) return;
    unsigned c = (unsigned)ei[N_EDGES + e];
    if (c < N_NODES) atomicAdd(&g_count[c], 1);
}

__global__ void dinv_kernel() {
    int i = blockIdx.x * blockDim.x + threadIdx.x;
    if (i >= N_NODES) return;
    int d = g_count[i];
    g_dinv[i] = (d > 0) ? rsqrtf((float)d) : 0.0f;
}

// ---- 3-kernel exclusive scan of g_count -> g_off ---------------------------
__global__ void scan1_kernel() {
    __shared__ int s[SCAN_B];
    int t = threadIdx.x;
    int i = blockIdx.x * SCAN_B + t;
    int v = (i < N_NODES) ? g_count[i] : 0;
    s[t] = v; __syncthreads();
    int x = v;
    for (int o = 1; o < SCAN_B; o <<= 1) {
        int y = (t >= o) ? s[t - o] : 0;
        __syncthreads();
        x += y; s[t] = x;
        __syncthreads();
    }
    if (i < N_NODES) g_off[i] = x - v;
    if (t == SCAN_B - 1) g_bsum[blockIdx.x] = x;
}

__global__ void scan2_kernel() {
    __shared__ int s[256];
    int t = threadIdx.x;
    int v = (t < NBLK) ? g_bsum[t] : 0;
    s[t] = v; __syncthreads();
    int x = v;
    for (int o = 1; o < 256; o <<= 1) {
        int y = (t >= o) ? s[t - o] : 0;
        __syncthreads();
        x += y; s[t] = x;
        __syncthreads();
    }
    if (t < NBLK) g_boff[t] = x - v;
}

__global__ void scan3_kernel() {
    int i = blockIdx.x * blockDim.x + threadIdx.x;
    if (i < N_NODES) g_off[i] += g_boff[i / SCAN_B];
    if (i == 0) g_off[N_NODES] = N_EDGES;
}

__global__ void scatter_kernel(const int* __restrict__ ei) {
    int e = blockIdx.x * blockDim.x + threadIdx.x;
    if (e >= N_EDGES) return;
    int r = ei[e];
    unsigned c = (unsigned)ei[N_EDGES + e];
    if (c >= N_NODES) return;
    int pos = g_off[c] + atomicAdd(&g_cursor[c], 1);
    g_src[pos] = r;
}

// ------- GEMM: h2[n] = half2( (X[n,:K] @ W) * dinv[n] ) ---------------------
// 256 thr = 8 nodes x 32 lanes; each lane computes feature pair (2l, 2l+1).
template <int K>
__global__ void gemm_kernel(const float* __restrict__ Xext,
                            const float* __restrict__ W, int src) {
    __shared__ float2 sW[K * 32];   // W[k][2l..2l+1]
    const float2* W2 = (const float2*)W;
    for (int i = threadIdx.x; i < K * 32; i += 256) sW[i] = W2[i];
    __syncthreads();

    int node = blockIdx.x * 8 + (threadIdx.x >> 5);
    int lane = threadIdx.x & 31;
    if (node >= N_NODES) return;

    const float* X = (src == 0) ? Xext : (src == 1) ? g_x1 : g_x2;
    const float* xr = X + (size_t)node * K;
    float a0 = 0.0f, a1 = 0.0f;
#pragma unroll 8
    for (int k = 0; k < K; k++) {
        float x = xr[k];                 // broadcast within warp (1 node/warp)
        float2 w = sW[k * 32 + lane];
        a0 = fmaf(x, w.x, a0);
        a1 = fmaf(x, w.y, a1);
    }
    float di = g_dinv[node];
    g_h2[node * 32 + lane] = __floats2half2_rn(a0 * di, a1 * di);
}

// ------- aggregate (CSR gather, fp16 payload) + bias + relu -----------------
// out[n,f] = relu( dinv[n] * sum_e h[src(e), f] + b[f] );  1 warp per node.
__global__ void aggregate_kernel(const float* __restrict__ b, int dst) {
    int node = blockIdx.x * 8 + (threadIdx.x >> 5);
    int lane = threadIdx.x & 31;
    if (node >= N_NODES) return;

    int beg = g_off[node], end = g_off[node + 1];
    float x0 = 0.f, y0 = 0.f, x1 = 0.f, y1 = 0.f;
    float x2 = 0.f, y2 = 0.f, x3 = 0.f, y3 = 0.f;
    int e = beg;
    for (; e + 4 <= end; e += 4) {                    // 4-way MLP
        int s0 = __ldg(&g_src[e + 0]);
        int s1 = __ldg(&g_src[e + 1]);
        int s2 = __ldg(&g_src[e + 2]);
        int s3 = __ldg(&g_src[e + 3]);
        float2 v0 = __half22float2(g_h2[s0 * 32 + lane]);
        float2 v1 = __half22float2(g_h2[s1 * 32 + lane]);
        float2 v2 = __half22float2(g_h2[s2 * 32 + lane]);
        float2 v3 = __half22float2(g_h2[s3 * 32 + lane]);
        x0 += v0.x; y0 += v0.y;
        x1 += v1.x; y1 += v1.y;
        x2 += v2.x; y2 += v2.y;
        x3 += v3.x; y3 += v3.y;
    }
    for (; e < end; e++) {
        float2 v = __half22float2(g_h2[__ldg(&g_src[e]) * 32 + lane]);
        x0 += v.x; y0 += v.y;
    }
    float ax = (x0 + x1) + (x2 + x3);
    float ay = (y0 + y1) + (y2 + y3);

    float di = g_dinv[node];
    int f = lane * 2;
    float vx = fmaxf(fmaf(ax, di, b[f + 0]), 0.0f);
    float vy = fmaxf(fmaf(ay, di, b[f + 1]), 0.0f);
    float2* out = (float2*)((dst == 1) ? g_x1 : (dst == 2) ? g_x2 : g_x3);
    out[node * 32 + lane] = make_float2(vx, vy);
}

// ---------------- pooling over sorted batch ---------------------------------
__global__ void start_mark_kernel() {
    int i = blockIdx.x * blockDim.x + threadIdx.x;
    if (i <= N_GRAPHS) g_start[i] = -1;
}

__global__ void start_set_kernel(const int* __restrict__ batch) {
    int i = blockIdx.x * blockDim.x + threadIdx.x;
    if (i >= N_NODES) return;
    int bcur = batch[i];
    if ((unsigned)bcur >= N_GRAPHS) return;
    if (i == 0 || batch[i - 1] != bcur) g_start[bcur] = i;
    if (i == 0) g_start[N_GRAPHS] = N_NODES;
}

__global__ void start_fix_kernel() {
    __shared__ int s[N_GRAPHS + 1];
    int t = threadIdx.x;
    for (int k = t; k <= N_GRAPHS; k += blockDim.x) s[k] = g_start[k];
    __syncthreads();
    if (t == 0) {
        int nxt = s[N_GRAPHS];
        for (int g = N_GRAPHS - 1; g >= 0; --g) {
            if (s[g] < 0) s[g] = nxt;
            nxt = s[g];
        }
    }
    __syncthreads();
    for (int k = t; k <= N_GRAPHS; k += blockDim.x) g_start[k] = s[k];
}

// one block (192 thr) per graph: mean over its contiguous node range
__global__ void pool_kernel() {
    int g = blockIdx.x;
    int t = threadIdx.x;                  // 0..191
    int beg = g_start[g], end = g_start[g + 1];
    const float* src = (t < 64) ? g_x1 : (t < 128) ? g_x2 : g_x3;
    int f = t & 63;
    float a0 = 0.f, a1 = 0.f, a2 = 0.f, a3 = 0.f;
    int n = beg;
    for (; n + 4 <= end; n += 4) {        // 4-way MLP
        a0 += src[(n + 0) * F_HID + f];
        a1 += src[(n + 1) * F_HID + f];
        a2 += src[(n + 2) * F_HID + f];
        a3 += src[(n + 3) * F_HID + f];
    }
    for (; n < end; n++) a0 += src[n * F_HID + f];
    float acc = (a0 + a1) + (a2 + a3);
    float cnt = (float)max(end - beg, 1);
    g_pool[g * (3 * F_HID) + t] = acc / cnt;
}

// one warp per graph: logits = pooled @ Wf + bf, softmax over 10
__global__ void final_kernel(const float* __restrict__ Wf,
                             const float* __restrict__ bf,
                             float* __restrict__ out) {
    int g = blockIdx.x;
    int j = threadIdx.x;
    float logit = __int_as_float(0xff800000);  // -inf
    if (j < F_OUT) {
        float acc = bf[j];
        const float* p = g_pool + g * (3 * F_HID);
#pragma unroll 16
        for (int k = 0; k < 3 * F_HID; k++)
            acc = fmaf(p[k], Wf[k * F_OUT + j], acc);
        logit = acc;
    }
    float m = logit;
    for (int o = 16; o; o >>= 1) m = fmaxf(m, __shfl_xor_sync(0xffffffff, m, o));
    float ex = (j < F_OUT) ? expf(logit - m) : 0.0f;
    float s = ex;
    for (int o = 16; o; o >>= 1) s += __shfl_xor_sync(0xffffffff, s, o);
    if (j < F_OUT) out[g * F_OUT + j] = ex / s;
}

// ---------------- launch -----------------------------------------------------
extern "C" void kernel_launch(void* const* d_in, const int* in_sizes, int n_in,
                              void* d_out, int out_size) {
    const float* X0    = (const float*)d_in[0];
    const int*   ei    = (const int*)d_in[1];    // int32 (JAX x64 disabled)
    const int*   batch = (const int*)d_in[2];
    const float* W1    = (const float*)d_in[3];
    const float* b1    = (const float*)d_in[4];
    const float* W2    = (const float*)d_in[5];
    const float* b2    = (const float*)d_in[6];
    const float* W3    = (const float*)d_in[7];
    const float* b3    = (const float*)d_in[8];
    const float* Wf    = (const float*)d_in[9];
    const float* bf    = (const float*)d_in[10];
    float* out = (float*)d_out;

    const int TB = 256;
    const int gridE = (N_EDGES + TB - 1) / TB;
    const int gridN = (N_NODES + TB - 1) / TB;
    const int grid8 = (N_NODES + 7) / 8;      // gemm / aggregate (8 nodes/blk)

    // --- CSR + norm prep ---
    zero_ints_kernel<<<256, TB>>>();
    count_kernel<<<gridE, TB>>>(ei);
    dinv_kernel<<<gridN, TB>>>();
    scan1_kernel<<<NBLK, SCAN_B>>>();
    scan2_kernel<<<1, 256>>>();
    scan3_kernel<<<gridN, TB>>>();
    scatter_kernel<<<gridE, TB>>>(ei);

    // --- graph boundaries (batch is sorted) ---
    start_mark_kernel<<<4, TB>>>();
    start_set_kernel<<<gridN, TB>>>(batch);
    start_fix_kernel<<<1, 256>>>();

    // --- layer 1 ---
    gemm_kernel<F_IN><<<grid8, TB>>>(X0, W1, 0);
    aggregate_kernel<<<grid8, TB>>>(b1, 1);
    // --- layer 2 ---
    gemm_kernel<F_HID><<<grid8, TB>>>(nullptr, W2, 1);
    aggregate_kernel<<<grid8, TB>>>(b2, 2);
    // --- layer 3 ---
    gemm_kernel<F_HID><<<grid8, TB>>>(nullptr, W3, 2);
    aggregate_kernel<<<grid8, TB>>>(b3, 3);

    // --- pooling + head ---
    pool_kernel<<<N_GRAPHS, 3 * F_HID>>>();
    final_kernel<<<N_GRAPHS, 32>>>(Wf, bf, out);
}

// round 6
// speedup vs baseline: 2.1621x; 1.4539x over previous
#include <cuda_runtime.h>
#include <cuda_fp16.h>
#include <math.h>

#define N_NODES  100000
#define N_EDGES  3200000
#define N_GRAPHS 512
#define F_IN     128
#define F_HID    64
#define F_OUT    10

#define SCAN_B   512
#define NBLK     ((N_NODES + SCAN_B - 1) / SCAN_B)   // 196

// GEMM tiling: 128 threads = 4 warps, 4 nodes/warp -> 16 nodes per tile
#define GEMM_TPB    128
#define GEMM_NODES  16
#define GEMM_GRID   1184      // 148 SMs * 8

// ---------------- scratch (device globals: no allocation allowed) ----------
__device__ int     g_count [N_NODES];
__device__ int     g_cursor[N_NODES];
__device__ int     g_off   [N_NODES + 1];
__device__ int     g_bsum  [NBLK];
__device__ int     g_boff  [NBLK];
__device__ int     g_src   [N_EDGES];
__device__ float   g_dinv  [N_NODES];
__device__ __half2 g_h2    [N_NODES * 32];        // h fp16, pre-scaled by dinv
__device__ float   g_x1    [N_NODES * F_HID];
__device__ float   g_x2    [N_NODES * F_HID];
__device__ float   g_x3    [N_NODES * F_HID];
__device__ int     g_start [N_GRAPHS + 1];
__device__ float   g_pool  [N_GRAPHS * 3 * F_HID];

// ---------------- prep -------------------------------------------------------
__global__ void zero_ints_kernel() {
    int i = blockIdx.x * blockDim.x + threadIdx.x;
    int stride = gridDim.x * blockDim.x;
    for (int k = i; k < N_NODES; k += stride) { g_count[k] = 0; g_cursor[k] = 0; }
}

__global__ void count_kernel(const int* __restrict__ ei) {
    int e = blockIdx.x * blockDim.x + threadIdx.x;
    if (e >= N_EDGES) return;
    unsigned c = (unsigned)ei[N_EDGES + e];
    if (c < N_NODES) atomicAdd(&g_count[c], 1);
}

__global__ void dinv_kernel() {
    int i = blockIdx.x * blockDim.x + threadIdx.x;
    if (i >= N_NODES) return;
    int d = g_count[i];
    g_dinv[i] = (d > 0) ? rsqrtf((float)d) : 0.0f;
}

// ---- 3-kernel exclusive scan of g_count -> g_off ---------------------------
__global__ void scan1_kernel() {
    __shared__ int s[SCAN_B];
    int t = threadIdx.x;
    int i = blockIdx.x * SCAN_B + t;
    int v = (i < N_NODES) ? g_count[i] : 0;
    s[t] = v; __syncthreads();
    int x = v;
    for (int o = 1; o < SCAN_B; o <<= 1) {
        int y = (t >= o) ? s[t - o] : 0;
        __syncthreads();
        x += y; s[t] = x;
        __syncthreads();
    }
    if (i < N_NODES) g_off[i] = x - v;
    if (t == SCAN_B - 1) g_bsum[blockIdx.x] = x;
}

__global__ void scan2_kernel() {
    __shared__ int s[256];
    int t = threadIdx.x;
    int v = (t < NBLK) ? g_bsum[t] : 0;
    s[t] = v; __syncthreads();
    int x = v;
    for (int o = 1; o < 256; o <<= 1) {
        int y = (t >= o) ? s[t - o] : 0;
        __syncthreads();
        x += y; s[t] = x;
        __syncthreads();
    }
    if (t < NBLK) g_boff[t] = x - v;
}

__global__ void scan3_kernel() {
    int i = blockIdx.x * blockDim.x + threadIdx.x;
    if (i < N_NODES) g_off[i] += g_boff[i / SCAN_B];
    if (i == 0) g_off[N_NODES] = N_EDGES;
}

__global__ void scatter_kernel(const int* __restrict__ ei) {
    int e = blockIdx.x * blockDim.x + threadIdx.x;
    if (e >= N_EDGES) return;
    int r = ei[e];
    unsigned c = (unsigned)ei[N_EDGES + e];
    if (c >= N_NODES) return;
    int pos = g_off[c] + atomicAdd(&g_cursor[c], 1);
    g_src[pos] = r;
}

// ------- GEMM: h2[n] = half2( (X[n,:K] @ W) * dinv[n] ) ---------------------
// Tile-persistent: weights loaded once per block; grid-stride over 16-node
// tiles. 4 warps x 4 nodes; lane = feature pair; 8 FMA + 5 LDS per k-iter.
template <int K>
__global__ __launch_bounds__(GEMM_TPB) void gemm_kernel(
        const float* __restrict__ Xext, const float* __restrict__ W, int src) {
    __shared__ float2 sW[K * 32];                // W[k][2l..2l+1]
    __shared__ float  sX[GEMM_NODES][K];

    const float2* W2 = (const float2*)W;
    for (int i = threadIdx.x; i < K * 32; i += GEMM_TPB) sW[i] = W2[i];

    const float* X = (src == 0) ? Xext : (src == 1) ? g_x1 : g_x2;
    int warp = threadIdx.x >> 5;
    int lane = threadIdx.x & 31;

    const int NTILES = N_NODES / GEMM_NODES;     // 6250 exactly
    for (int tile = blockIdx.x; tile < NTILES; tile += gridDim.x) {
        int node0 = tile * GEMM_NODES;
        __syncthreads();                         // protect sX reuse
        // stage X tile: 16*K floats, coalesced float4
        const float4* Xs = (const float4*)(X + (size_t)node0 * K);
        float4* sX4 = (float4*)&sX[0][0];
        for (int i = threadIdx.x; i < GEMM_NODES * K / 4; i += GEMM_TPB)
            sX4[i] = Xs[i];
        __syncthreads();

        int nb = warp * 4;                       // 4 nodes per warp
        float2 a0 = {0,0}, a1 = {0,0}, a2 = {0,0}, a3 = {0,0};
#pragma unroll 4
        for (int k = 0; k < K; k++) {
            float2 w = sW[k * 32 + lane];
            float x0 = sX[nb + 0][k];
            float x1 = sX[nb + 1][k];
            float x2 = sX[nb + 2][k];
            float x3 = sX[nb + 3][k];
            a0.x = fmaf(x0, w.x, a0.x); a0.y = fmaf(x0, w.y, a0.y);
            a1.x = fmaf(x1, w.x, a1.x); a1.y = fmaf(x1, w.y, a1.y);
            a2.x = fmaf(x2, w.x, a2.x); a2.y = fmaf(x2, w.y, a2.y);
            a3.x = fmaf(x3, w.x, a3.x); a3.y = fmaf(x3, w.y, a3.y);
        }
        int n = node0 + nb;
        float d0 = g_dinv[n + 0], d1 = g_dinv[n + 1];
        float d2 = g_dinv[n + 2], d3 = g_dinv[n + 3];
        g_h2[(n + 0) * 32 + lane] = __floats2half2_rn(a0.x * d0, a0.y * d0);
        g_h2[(n + 1) * 32 + lane] = __floats2half2_rn(a1.x * d1, a1.y * d1);
        g_h2[(n + 2) * 32 + lane] = __floats2half2_rn(a2.x * d2, a2.y * d2);
        g_h2[(n + 3) * 32 + lane] = __floats2half2_rn(a3.x * d3, a3.y * d3);
    }
}

// ------- aggregate (CSR gather, fp16 payload) + bias + relu -----------------
// 1 warp/node, lane = feature pair. int4 index loads, 8-edge unroll (MLP 8).
__global__ void aggregate_kernel(const float* __restrict__ b, int dst) {
    int node = blockIdx.x * 8 + (threadIdx.x >> 5);
    int lane = threadIdx.x & 31;
    if (node >= N_NODES) return;

    int beg = g_off[node], end = g_off[node + 1];
    float ax = 0.f, ay = 0.f, bx = 0.f, by = 0.f;
    int e = beg;
    // scalar prologue to 16B alignment of &g_src[e]
    for (; e < end && (e & 3); e++) {
        float2 v = __half22float2(__ldg(&g_h2[__ldg(&g_src[e]) * 32 + lane]));
        ax += v.x; ay += v.y;
    }
    const int4* s4 = (const int4*)g_src;
    for (; e + 8 <= end; e += 8) {
        int4 i0 = __ldg(&s4[e >> 2]);
        int4 i1 = __ldg(&s4[(e >> 2) + 1]);
        float2 v0 = __half22float2(__ldg(&g_h2[i0.x * 32 + lane]));
        float2 v1 = __half22float2(__ldg(&g_h2[i0.y * 32 + lane]));
        float2 v2 = __half22float2(__ldg(&g_h2[i0.z * 32 + lane]));
        float2 v3 = __half22float2(__ldg(&g_h2[i0.w * 32 + lane]));
        float2 v4 = __half22float2(__ldg(&g_h2[i1.x * 32 + lane]));
        float2 v5 = __half22float2(__ldg(&g_h2[i1.y * 32 + lane]));
        float2 v6 = __half22float2(__ldg(&g_h2[i1.z * 32 + lane]));
        float2 v7 = __half22float2(__ldg(&g_h2[i1.w * 32 + lane]));
        ax += v0.x + v2.x + v4.x + v6.x;  ay += v0.y + v2.y + v4.y + v6.y;
        bx += v1.x + v3.x + v5.x + v7.x;  by += v1.y + v3.y + v5.y + v7.y;
    }
    if (e + 4 <= end) {
        int4 i0 = __ldg(&s4[e >> 2]);
        float2 v0 = __half22float2(__ldg(&g_h2[i0.x * 32 + lane]));
        float2 v1 = __half22float2(__ldg(&g_h2[i0.y * 32 + lane]));
        float2 v2 = __half22float2(__ldg(&g_h2[i0.z * 32 + lane]));
        float2 v3 = __half22float2(__ldg(&g_h2[i0.w * 32 + lane]));
        ax += v0.x + v2.x;  ay += v0.y + v2.y;
        bx += v1.x + v3.x;  by += v1.y + v3.y;
        e += 4;
    }
    for (; e < end; e++) {
        float2 v = __half22float2(__ldg(&g_h2[__ldg(&g_src[e]) * 32 + lane]));
        ax += v.x; ay += v.y;
    }
    float sx = ax + bx, sy = ay + by;

    float di = g_dinv[node];
    int f = lane * 2;
    float vx = fmaxf(fmaf(sx, di, b[f + 0]), 0.0f);
    float vy = fmaxf(fmaf(sy, di, b[f + 1]), 0.0f);
    float2* out = (float2*)((dst == 1) ? g_x1 : (dst == 2) ? g_x2 : g_x3);
    out[node * 32 + lane] = make_float2(vx, vy);
}

// ---------------- pooling over sorted batch ---------------------------------
__global__ void start_mark_kernel() {
    int i = blockIdx.x * blockDim.x + threadIdx.x;
    if (i <= N_GRAPHS) g_start[i] = -1;
}

__global__ void start_set_kernel(const int* __restrict__ batch) {
    int i = blockIdx.x * blockDim.x + threadIdx.x;
    if (i >= N_NODES) return;
    int bcur = batch[i];
    if ((unsigned)bcur >= N_GRAPHS) return;
    if (i == 0 || batch[i - 1] != bcur) g_start[bcur] = i;
    if (i == 0) g_start[N_GRAPHS] = N_NODES;
}

__global__ void start_fix_kernel() {
    __shared__ int s[N_GRAPHS + 1];
    int t = threadIdx.x;
    for (int k = t; k <= N_GRAPHS; k += blockDim.x) s[k] = g_start[k];
    __syncthreads();
    if (t == 0) {
        int nxt = s[N_GRAPHS];
        for (int g = N_GRAPHS - 1; g >= 0; --g) {
            if (s[g] < 0) s[g] = nxt;
            nxt = s[g];
        }
    }
    __syncthreads();
    for (int k = t; k <= N_GRAPHS; k += blockDim.x) g_start[k] = s[k];
}

// one block (96 thr) per graph: float2 mean over contiguous node range
__global__ void pool_kernel() {
    int g = blockIdx.x;
    int t = threadIdx.x;                  // 0..95
    int layer = t >> 5, p = t & 31;
    int beg = g_start[g], end = g_start[g + 1];
    const float2* src = (layer == 0) ? (const float2*)g_x1
                       : (layer == 1) ? (const float2*)g_x2
                                      : (const float2*)g_x3;
    float x0 = 0.f, y0 = 0.f, x1 = 0.f, y1 = 0.f;
    float x2 = 0.f, y2 = 0.f, x3 = 0.f, y3 = 0.f;
    int n = beg;
    for (; n + 4 <= end; n += 4) {        // 4-way MLP
        float2 v0 = src[(n + 0) * 32 + p];
        float2 v1 = src[(n + 1) * 32 + p];
        float2 v2 = src[(n + 2) * 32 + p];
        float2 v3 = src[(n + 3) * 32 + p];
        x0 += v0.x; y0 += v0.y;  x1 += v1.x; y1 += v1.y;
        x2 += v2.x; y2 += v2.y;  x3 += v3.x; y3 += v3.y;
    }
    for (; n < end; n++) { float2 v = src[n * 32 + p]; x0 += v.x; y0 += v.y; }
    float inv = 1.0f / (float)max(end - beg, 1);
    float2* dst = (float2*)&g_pool[g * (3 * F_HID)];
    dst[layer * 32 + p] = make_float2(((x0 + x1) + (x2 + x3)) * inv,
                                      ((y0 + y1) + (y2 + y3)) * inv);
}

// one warp per graph: logits = pooled @ Wf + bf, softmax over 10
__global__ void final_kernel(const float* __restrict__ Wf,
                             const float* __restrict__ bf,
                             float* __restrict__ out) {
    int g = blockIdx.x;
    int j = threadIdx.x;
    float logit = __int_as_float(0xff800000);  // -inf
    if (j < F_OUT) {
        float acc = bf[j];
        const float* p = g_pool + g * (3 * F_HID);
#pragma unroll 16
        for (int k = 0; k < 3 * F_HID; k++)
            acc = fmaf(p[k], Wf[k * F_OUT + j], acc);
        logit = acc;
    }
    float m = logit;
    for (int o = 16; o; o >>= 1) m = fmaxf(m, __shfl_xor_sync(0xffffffff, m, o));
    float ex = (j < F_OUT) ? expf(logit - m) : 0.0f;
    float s = ex;
    for (int o = 16; o; o >>= 1) s += __shfl_xor_sync(0xffffffff, s, o);
    if (j < F_OUT) out[g * F_OUT + j] = ex / s;
}

// ---------------- launch -----------------------------------------------------
extern "C" void kernel_launch(void* const* d_in, const int* in_sizes, int n_in,
                              void* d_out, int out_size) {
    const float* X0    = (const float*)d_in[0];
    const int*   ei    = (const int*)d_in[1];    // int32 (JAX x64 disabled)
    const int*   batch = (const int*)d_in[2];
    const float* W1    = (const float*)d_in[3];
    const float* b1    = (const float*)d_in[4];
    const float* W2    = (const float*)d_in[5];
    const float* b2    = (const float*)d_in[6];
    const float* W3    = (const float*)d_in[7];
    const float* b3    = (const float*)d_in[8];
    const float* Wf    = (const float*)d_in[9];
    const float* bf    = (const float*)d_in[10];
    float* out = (float*)d_out;

    const int TB = 256;
    const int gridE = (N_EDGES + TB - 1) / TB;
    const int gridN = (N_NODES + TB - 1) / TB;
    const int grid8 = (N_NODES + 7) / 8;      // aggregate: 8 nodes/block

    // --- CSR + norm prep ---
    zero_ints_kernel<<<256, TB>>>();
    count_kernel<<<gridE, TB>>>(ei);
    dinv_kernel<<<gridN, TB>>>();
    scan1_kernel<<<NBLK, SCAN_B>>>();
    scan2_kernel<<<1, 256>>>();
    scan3_kernel<<<gridN, TB>>>();
    scatter_kernel<<<gridE, TB>>>(ei);

    // --- graph boundaries (batch is sorted) ---
    start_mark_kernel<<<4, TB>>>();
    start_set_kernel<<<gridN, TB>>>(batch);
    start_fix_kernel<<<1, 256>>>();

    // --- layer 1 ---
    gemm_kernel<F_IN><<<GEMM_GRID, GEMM_TPB>>>(X0, W1, 0);
    aggregate_kernel<<<grid8, TB>>>(b1, 1);
    // --- layer 2 ---
    gemm_kernel<F_HID><<<GEMM_GRID, GEMM_TPB>>>(nullptr, W2, 1);
    aggregate_kernel<<<grid8, TB>>>(b2, 2);
    // --- layer 3 ---
    gemm_kernel<F_HID><<<GEMM_GRID, GEMM_TPB>>>(nullptr, W3, 2);
    aggregate_kernel<<<grid8, TB>>>(b3, 3);

    // --- pooling + head ---
    pool_kernel<<<N_GRAPHS, 96>>>();
    final_kernel<<<N_GRAPHS, 32>>>(Wf, bf, out);
}

// round 7
// speedup vs baseline: 2.3133x; 1.0699x over previous
#include <cuda_runtime.h>
#include <cuda_fp16.h>
#include <math.h>

#define N_NODES  100000
#define N_EDGES  3200000
#define N_GRAPHS 512
#define F_IN     128
#define F_HID    64
#define F_OUT    10

#define SCAN_B   512
#define NBLK     ((N_NODES + SCAN_B - 1) / SCAN_B)   // 196

// GEMM tiling: 128 threads = 4 warps, 4 nodes/warp -> 16 nodes per tile
#define GEMM_TPB    128
#define GEMM_NODES  16
#define GEMM_GRID   1184

// ---------------- scratch (device globals: no allocation allowed) ----------
__device__ int     g_count [N_NODES];
__device__ int     g_cursor[N_NODES];
__device__ int     g_off   [N_NODES + 1];
__device__ int     g_bsum  [NBLK];
__device__ int     g_boff  [NBLK];
__device__ int     g_src   [N_EDGES];
__device__ float   g_dinv  [N_NODES];
__device__ __half2 g_h2    [N_NODES * 32];   // messages, fp16, pre-scaled
__device__ __half2 g_xh1   [N_NODES * 32];   // layer activations, fp16
__device__ __half2 g_xh2   [N_NODES * 32];
__device__ __half2 g_xh3   [N_NODES * 32];
__device__ int     g_start [N_GRAPHS + 1];
__device__ float   g_pool  [N_GRAPHS * 3 * F_HID];

// ---------------- packed f32x2 helpers --------------------------------------
__device__ __forceinline__ void ffma2(unsigned long long& acc, float x,
                                      unsigned long long w) {
    unsigned long long xx;
    asm("mov.b64 %0, {%1, %1};" : "=l"(xx) : "f"(x));           // ALU pipe
    asm("fma.rn.f32x2 %0, %1, %2, %0;" : "+l"(acc) : "l"(xx), "l"(w));
}
__device__ __forceinline__ float2 unpack2(unsigned long long v) {
    float2 r;
    asm("mov.b64 {%0, %1}, %2;" : "=f"(r.x), "=f"(r.y) : "l"(v));
    return r;
}

// ---------------- prep -------------------------------------------------------
__global__ void init_kernel() {
    int i = blockIdx.x * blockDim.x + threadIdx.x;
    int stride = gridDim.x * blockDim.x;
    for (int k = i; k < N_NODES; k += stride) { g_count[k] = 0; g_cursor[k] = 0; }
    for (int k = i; k <= N_GRAPHS; k += stride) g_start[k] = -1;
}

__global__ void count_kernel(const int* __restrict__ ei) {
    int e = blockIdx.x * blockDim.x + threadIdx.x;
    if (e >= N_EDGES) return;
    unsigned c = (unsigned)ei[N_EDGES + e];
    if (c < N_NODES) atomicAdd(&g_count[c], 1);
}

// ---- scan of g_count -> g_off; dinv fused ----------------------------------
__global__ void scan1_kernel() {
    __shared__ int s[SCAN_B];
    int t = threadIdx.x;
    int i = blockIdx.x * SCAN_B + t;
    int v = (i < N_NODES) ? g_count[i] : 0;
    if (i < N_NODES) g_dinv[i] = (v > 0) ? rsqrtf((float)v) : 0.0f;
    s[t] = v; __syncthreads();
    int x = v;
    for (int o = 1; o < SCAN_B; o <<= 1) {
        int y = (t >= o) ? s[t - o] : 0;
        __syncthreads();
        x += y; s[t] = x;
        __syncthreads();
    }
    if (i < N_NODES) g_off[i] = x - v;
    if (t == SCAN_B - 1) g_bsum[blockIdx.x] = x;
}

__global__ void scan2_kernel() {
    __shared__ int s[256];
    int t = threadIdx.x;
    int v = (t < NBLK) ? g_bsum[t] : 0;
    s[t] = v; __syncthreads();
    int x = v;
    for (int o = 1; o < 256; o <<= 1) {
        int y = (t >= o) ? s[t - o] : 0;
        __syncthreads();
        x += y; s[t] = x;
        __syncthreads();
    }
    if (t < NBLK) g_boff[t] = x - v;
}

__global__ void scan3_kernel() {
    int i = blockIdx.x * blockDim.x + threadIdx.x;
    if (i < N_NODES) g_off[i] += g_boff[i / SCAN_B];
    if (i == 0) g_off[N_NODES] = N_EDGES;
}

__global__ void scatter_kernel(const int* __restrict__ ei) {
    int e = blockIdx.x * blockDim.x + threadIdx.x;
    if (e >= N_EDGES) return;
    int r = ei[e];
    unsigned c = (unsigned)ei[N_EDGES + e];
    if (c >= N_NODES) return;
    int pos = g_off[c] + atomicAdd(&g_cursor[c], 1);
    g_src[pos] = r;
}

// ------- GEMM: h2[n] = half2( (X[n,:K] @ W) * dinv[n] ) ---------------------
// Persistent tiles; FFMA2 packed math. src: 0 -> Xext fp32, 1 -> g_xh1,
// 2 -> g_xh2 (half2).
template <int K>
__global__ __launch_bounds__(GEMM_TPB) void gemm_kernel(
        const float* __restrict__ Xext, const float* __restrict__ W, int src) {
    constexpr int K2 = K / 2;
    __shared__ ulonglong2 sW[K2 * 32];          // {W[2k2][2l..+1], W[2k2+1][..]}
    __shared__ float2     sX[GEMM_NODES * K2];  // x pairs per node

    const unsigned long long* Wu = (const unsigned long long*)W;
    for (int i = threadIdx.x; i < K2 * 32; i += GEMM_TPB) {
        int k2 = i >> 5, l = i & 31;
        sW[i] = make_ulonglong2(Wu[(2 * k2) * 32 + l], Wu[(2 * k2 + 1) * 32 + l]);
    }

    const __half2* Xh = (src == 1) ? g_xh1 : g_xh2;
    int warp = threadIdx.x >> 5;
    int lane = threadIdx.x & 31;

    const int NTILES = N_NODES / GEMM_NODES;    // 6250 exactly
    for (int tile = blockIdx.x; tile < NTILES; tile += gridDim.x) {
        int node0 = tile * GEMM_NODES;
        __syncthreads();
        if (src == 0) {
            const float4* s = (const float4*)(Xext + (size_t)node0 * K);
            float4* d = (float4*)sX;
            for (int i = threadIdx.x; i < GEMM_NODES * K / 4; i += GEMM_TPB)
                d[i] = s[i];
        } else {
            const __half2* s = Xh + (size_t)node0 * 32;
            for (int i = threadIdx.x; i < GEMM_NODES * 32; i += GEMM_TPB)
                sX[i] = __half22float2(s[i]);
        }
        __syncthreads();

        int nb = warp * 4;
        unsigned long long a0 = 0, a1 = 0, a2 = 0, a3 = 0; // {0.f,0.f}
        const float2* x0p = &sX[(nb + 0) * K2];
        const float2* x1p = &sX[(nb + 1) * K2];
        const float2* x2p = &sX[(nb + 2) * K2];
        const float2* x3p = &sX[(nb + 3) * K2];
#pragma unroll 8
        for (int k2 = 0; k2 < K2; k2++) {
            ulonglong2 w = sW[k2 * 32 + lane];
            float2 x0 = x0p[k2], x1 = x1p[k2], x2 = x2p[k2], x3 = x3p[k2];
            ffma2(a0, x0.x, w.x); ffma2(a0, x0.y, w.y);
            ffma2(a1, x1.x, w.x); ffma2(a1, x1.y, w.y);
            ffma2(a2, x2.x, w.x); ffma2(a2, x2.y, w.y);
            ffma2(a3, x3.x, w.x); ffma2(a3, x3.y, w.y);
        }
        int n = node0 + nb;
        float2 f0 = unpack2(a0), f1 = unpack2(a1);
        float2 f2 = unpack2(a2), f3 = unpack2(a3);
        float d0 = g_dinv[n + 0], d1 = g_dinv[n + 1];
        float d2 = g_dinv[n + 2], d3 = g_dinv[n + 3];
        g_h2[(n + 0) * 32 + lane] = __floats2half2_rn(f0.x * d0, f0.y * d0);
        g_h2[(n + 1) * 32 + lane] = __floats2half2_rn(f1.x * d1, f1.y * d1);
        g_h2[(n + 2) * 32 + lane] = __floats2half2_rn(f2.x * d2, f2.y * d2);
        g_h2[(n + 3) * 32 + lane] = __floats2half2_rn(f3.x * d3, f3.y * d3);
    }
}

// ------- aggregate (CSR gather, fp16) + bias + relu + fp16 pack --------------
__global__ void aggregate_kernel(const float* __restrict__ b, int dst) {
    int node = blockIdx.x * 8 + (threadIdx.x >> 5);
    int lane = threadIdx.x & 31;
    if (node >= N_NODES) return;

    int beg = g_off[node], end = g_off[node + 1];
    float ax = 0.f, ay = 0.f, bx = 0.f, by = 0.f;
    int e = beg;
    for (; e < end && (e & 3); e++) {
        float2 v = __half22float2(__ldg(&g_h2[__ldg(&g_src[e]) * 32 + lane]));
        ax += v.x; ay += v.y;
    }
    const int4* s4 = (const int4*)g_src;
    for (; e + 8 <= end; e += 8) {
        int4 i0 = __ldg(&s4[e >> 2]);
        int4 i1 = __ldg(&s4[(e >> 2) + 1]);
        float2 v0 = __half22float2(__ldg(&g_h2[i0.x * 32 + lane]));
        float2 v1 = __half22float2(__ldg(&g_h2[i0.y * 32 + lane]));
        float2 v2 = __half22float2(__ldg(&g_h2[i0.z * 32 + lane]));
        float2 v3 = __half22float2(__ldg(&g_h2[i0.w * 32 + lane]));
        float2 v4 = __half22float2(__ldg(&g_h2[i1.x * 32 + lane]));
        float2 v5 = __half22float2(__ldg(&g_h2[i1.y * 32 + lane]));
        float2 v6 = __half22float2(__ldg(&g_h2[i1.z * 32 + lane]));
        float2 v7 = __half22float2(__ldg(&g_h2[i1.w * 32 + lane]));
        ax += v0.x + v2.x + v4.x + v6.x;  ay += v0.y + v2.y + v4.y + v6.y;
        bx += v1.x + v3.x + v5.x + v7.x;  by += v1.y + v3.y + v5.y + v7.y;
    }
    if (e + 4 <= end) {
        int4 i0 = __ldg(&s4[e >> 2]);
        float2 v0 = __half22float2(__ldg(&g_h2[i0.x * 32 + lane]));
        float2 v1 = __half22float2(__ldg(&g_h2[i0.y * 32 + lane]));
        float2 v2 = __half22float2(__ldg(&g_h2[i0.z * 32 + lane]));
        float2 v3 = __half22float2(__ldg(&g_h2[i0.w * 32 + lane]));
        ax += v0.x + v2.x;  ay += v0.y + v2.y;
        bx += v1.x + v3.x;  by += v1.y + v3.y;
        e += 4;
    }
    for (; e < end; e++) {
        float2 v = __half22float2(__ldg(&g_h2[__ldg(&g_src[e]) * 32 + lane]));
        ax += v.x; ay += v.y;
    }
    float sx = ax + bx, sy = ay + by;

    float di = g_dinv[node];
    int f = lane * 2;
    float vx = fmaxf(fmaf(sx, di, b[f + 0]), 0.0f);
    float vy = fmaxf(fmaf(sy, di, b[f + 1]), 0.0f);
    __half2* out = (dst == 1) ? g_xh1 : (dst == 2) ? g_xh2 : g_xh3;
    out[node * 32 + lane] = __floats2half2_rn(vx, vy);
}

// ---------------- pooling over sorted batch ---------------------------------
__global__ void start_set_kernel(const int* __restrict__ batch) {
    int i = blockIdx.x * blockDim.x + threadIdx.x;
    if (i >= N_NODES) return;
    int bcur = batch[i];
    if ((unsigned)bcur >= N_GRAPHS) return;
    if (i == 0 || batch[i - 1] != bcur) g_start[bcur] = i;
    if (i == 0) g_start[N_GRAPHS] = N_NODES;
}

__global__ void start_fix_kernel() {
    __shared__ int s[N_GRAPHS + 1];
    int t = threadIdx.x;
    for (int k = t; k <= N_GRAPHS; k += blockDim.x) s[k] = g_start[k];
    __syncthreads();
    if (t == 0) {
        int nxt = s[N_GRAPHS];
        for (int g = N_GRAPHS - 1; g >= 0; --g) {
            if (s[g] < 0) s[g] = nxt;
            nxt = s[g];
        }
    }
    __syncthreads();
    for (int k = t; k <= N_GRAPHS; k += blockDim.x) g_start[k] = s[k];
}

// one block (96 thr) per graph: mean over contiguous node range (half2 in)
__global__ void pool_kernel() {
    int g = blockIdx.x;
    int t = threadIdx.x;                  // 0..95
    int layer = t >> 5, p = t & 31;
    int beg = g_start[g], end = g_start[g + 1];
    const __half2* src = (layer == 0) ? g_xh1 : (layer == 1) ? g_xh2 : g_xh3;
    float x0 = 0.f, y0 = 0.f, x1 = 0.f, y1 = 0.f;
    float x2 = 0.f, y2 = 0.f, x3 = 0.f, y3 = 0.f;
    int n = beg;
    for (; n + 4 <= end; n += 4) {
        float2 v0 = __half22float2(src[(n + 0) * 32 + p]);
        float2 v1 = __half22float2(src[(n + 1) * 32 + p]);
        float2 v2 = __half22float2(src[(n + 2) * 32 + p]);
        float2 v3 = __half22float2(src[(n + 3) * 32 + p]);
        x0 += v0.x; y0 += v0.y;  x1 += v1.x; y1 += v1.y;
        x2 += v2.x; y2 += v2.y;  x3 += v3.x; y3 += v3.y;
    }
    for (; n < end; n++) {
        float2 v = __half22float2(src[n * 32 + p]);
        x0 += v.x; y0 += v.y;
    }
    float inv = 1.0f / (float)max(end - beg, 1);
    float2* dst = (float2*)&g_pool[g * (3 * F_HID)];
    dst[layer * 32 + p] = make_float2(((x0 + x1) + (x2 + x3)) * inv,
                                      ((y0 + y1) + (y2 + y3)) * inv);
}

// one warp per graph: logits = pooled @ Wf + bf, softmax over 10
__global__ void final_kernel(const float* __restrict__ Wf,
                             const float* __restrict__ bf,
                             float* __restrict__ out) {
    int g = blockIdx.x;
    int j = threadIdx.x;
    float logit = __int_as_float(0xff800000);
    if (j < F_OUT) {
        float acc = bf[j];
        const float* p = g_pool + g * (3 * F_HID);
#pragma unroll 16
        for (int k = 0; k < 3 * F_HID; k++)
            acc = fmaf(p[k], Wf[k * F_OUT + j], acc);
        logit = acc;
    }
    float m = logit;
    for (int o = 16; o; o >>= 1) m = fmaxf(m, __shfl_xor_sync(0xffffffff, m, o));
    float ex = (j < F_OUT) ? expf(logit - m) : 0.0f;
    float s = ex;
    for (int o = 16; o; o >>= 1) s += __shfl_xor_sync(0xffffffff, s, o);
    if (j < F_OUT) out[g * F_OUT + j] = ex / s;
}

// ---------------- launch -----------------------------------------------------
extern "C" void kernel_launch(void* const* d_in, const int* in_sizes, int n_in,
                              void* d_out, int out_size) {
    const float* X0    = (const float*)d_in[0];
    const int*   ei    = (const int*)d_in[1];    // int32 (JAX x64 disabled)
    const int*   batch = (const int*)d_in[2];
    const float* W1    = (const float*)d_in[3];
    const float* b1    = (const float*)d_in[4];
    const float* W2    = (const float*)d_in[5];
    const float* b2    = (const float*)d_in[6];
    const float* W3    = (const float*)d_in[7];
    const float* b3    = (const float*)d_in[8];
    const float* Wf    = (const float*)d_in[9];
    const float* bf    = (const float*)d_in[10];
    float* out = (float*)d_out;

    const int TB = 256;
    const int gridE = (N_EDGES + TB - 1) / TB;
    const int gridN = (N_NODES + TB - 1) / TB;
    const int grid8 = (N_NODES + 7) / 8;

    // --- CSR + norm prep ---
    init_kernel<<<256, TB>>>();
    count_kernel<<<gridE, TB>>>(ei);
    scan1_kernel<<<NBLK, SCAN_B>>>();
    scan2_kernel<<<1, 256>>>();
    scan3_kernel<<<gridN, TB>>>();
    scatter_kernel<<<gridE, TB>>>(ei);

    // --- graph boundaries (batch is sorted) ---
    start_set_kernel<<<gridN, TB>>>(batch);
    start_fix_kernel<<<1, 256>>>();

    // --- layers ---
    gemm_kernel<F_IN><<<GEMM_GRID, GEMM_TPB>>>(X0, W1, 0);
    aggregate_kernel<<<grid8, TB>>>(b1, 1);
    gemm_kernel<F_HID><<<GEMM_GRID, GEMM_TPB>>>(nullptr, W2, 1);
    aggregate_kernel<<<grid8, TB>>>(b2, 2);
    gemm_kernel<F_HID><<<GEMM_GRID, GEMM_TPB>>>(nullptr, W3, 2);
    aggregate_kernel<<<grid8, TB>>>(b3, 3);

    // --- pooling + head ---
    pool_kernel<<<N_GRAPHS, 96>>>();
    final_kernel<<<N_GRAPHS, 32>>>(Wf, bf, out);
}